// round 14
// baseline (speedup 1.0000x reference)
#include <cuda_runtime.h>
#include <cuda_bf16.h>
#include <mma.h>
#include <cstdint>

using namespace nvcuda;

#define Bn 32
#define En 512
#define Nn 4096
#define IMG 224

#define KC 64                    // K elements per chunk
#define KSPLIT 4
#define CHUNKS_PER_ITEM 16       // 64 chunks / 4 splits
#define STAGES 3
#define LDT 72                   // padded smem leading dim (elements)
#define TILE_BYTES (128 * LDT * 2)          // 18432 per operand tile
#define STAGE_BYTES (2 * TILE_BYTES)        // 36864 (A + B)
#define GEMM_SMEM (STAGES * STAGE_BYTES)    // 110592
#define STG_PITCH 68             // epilogue staging pitch (fp32 elems, 16B mult)

#define BSPLIT_A 14              // 560 CTAs = 2 waves at 296 slots (R10-proven)
#define BSPLIT_B (Bn - BSPLIT_A) // 720 CTAs = 3 waves

// ----------------------------- device scratch -----------------------------
__device__ __nv_bfloat16 g_xbf[(size_t)Bn * En * Nn];         // 134 MB bf16 copy
__device__ float g_mean[Bn * En];                              // row means
__device__ float g_inv[Bn * En];                               // 1/(||x-mean||+1e-8)
__device__ float g_spatial[Bn * Nn];                           // column means
__device__ __nv_bfloat16 g_partb[(size_t)KSPLIT * Bn * En * En]; // 67 MB Gram partials (bf16)
__device__ unsigned g_mm[6];                                   // encoded min/max per view

// ----------------------------- helpers -----------------------------
__device__ __forceinline__ unsigned fenc(float f) {
    unsigned u = __float_as_uint(f);
    return (u & 0x80000000u) ? ~u : (u | 0x80000000u);
}
__device__ __forceinline__ float fdec(unsigned e) {
    return (e & 0x80000000u) ? __uint_as_float(e ^ 0x80000000u)
                             : __uint_as_float(~e);
}
__device__ __forceinline__ uint32_t s2u(const void* p) {
    uint32_t a;
    asm("{ .reg .u64 t; cvta.to.shared.u64 t, %1; cvt.u32.u64 %0, t; }"
        : "=r"(a) : "l"(p));
    return a;
}
__device__ __forceinline__ void cp16(uint32_t dst, const void* src) {
    asm volatile("cp.async.cg.shared.global [%0], [%1], 16;" :: "r"(dst), "l"(src));
}
__device__ __forceinline__ void cp_commit() {
    asm volatile("cp.async.commit_group;" ::: "memory");
}
__device__ __forceinline__ void cp_wait1() {
    asm volatile("cp.async.wait_group 1;" ::: "memory");
}
__device__ __forceinline__ void cp_wait0() {
    asm volatile("cp.async.wait_group 0;" ::: "memory");
}

// ----------------------------- kernel 0: init -----------------------------
__global__ void k_init() {
    int t = threadIdx.x;
    if (t < 6) g_mm[t] = (t & 1) ? 0u : 0xFFFFFFFFu;
}

// ------------------- kernel 1: row stats + bf16 convert (row ranges) -------------------
__global__ void __launch_bounds__(256) k_rowstats(const float* __restrict__ x, int roff) {
    const int row = blockIdx.x + roff;
    const float4* src = reinterpret_cast<const float4*>(x) + (size_t)row * (Nn / 4);
    uint2* dst = reinterpret_cast<uint2*>(g_xbf) + (size_t)row * (Nn / 4);
    float s = 0.f, ss = 0.f;
#pragma unroll
    for (int k = 0; k < 4; k++) {
        int i = threadIdx.x + k * 256;
        float4 v = src[i];
        s += v.x + v.y + v.z + v.w;
        ss += v.x * v.x + v.y * v.y + v.z * v.z + v.w * v.w;
        unsigned ax = (unsigned)__bfloat16_as_ushort(__float2bfloat16_rn(v.x));
        unsigned ay = (unsigned)__bfloat16_as_ushort(__float2bfloat16_rn(v.y));
        unsigned az = (unsigned)__bfloat16_as_ushort(__float2bfloat16_rn(v.z));
        unsigned aw = (unsigned)__bfloat16_as_ushort(__float2bfloat16_rn(v.w));
        uint2 o;
        o.x = ax | (ay << 16);
        o.y = az | (aw << 16);
        dst[i] = o;
    }
#pragma unroll
    for (int o = 16; o; o >>= 1) {
        s += __shfl_down_sync(0xFFFFFFFFu, s, o);
        ss += __shfl_down_sync(0xFFFFFFFFu, ss, o);
    }
    __shared__ float sh[16];
    int w = threadIdx.x >> 5, l = threadIdx.x & 31;
    if (l == 0) { sh[w] = s; sh[w + 8] = ss; }
    __syncthreads();
    if (threadIdx.x == 0) {
        float S = 0.f, SS = 0.f;
#pragma unroll
        for (int i = 0; i < 8; i++) { S += sh[i]; SS += sh[i + 8]; }
        float m = S * (1.f / (float)Nn);
        g_mean[row] = m;
        float var = SS - S * m;
        float r = sqrtf(fmaxf(var, 0.f));
        g_inv[row] = 1.f / (r + 1e-8f);
    }
}

// ------------------ kernel 2: column means (from bf16 copy) ------------------
__global__ void __launch_bounds__(256) k_colmean() {
    int T = blockIdx.x * 256 + threadIdx.x;   // 0..32767
    int b = T >> 10;                           // batch
    int g = T & 1023;                          // 4-column group
    const uint2* p = reinterpret_cast<const uint2*>(g_xbf + (size_t)b * En * Nn) + g;
    float s0 = 0.f, s1 = 0.f, s2 = 0.f, s3 = 0.f;
#pragma unroll 8
    for (int e = 0; e < En; e++) {
        uint2 v = p[(size_t)e * (Nn / 4)];
        s0 += __uint_as_float(v.x << 16);
        s1 += __uint_as_float(v.x & 0xFFFF0000u);
        s2 += __uint_as_float(v.y << 16);
        s3 += __uint_as_float(v.y & 0xFFFF0000u);
    }
    float4 o;
    o.x = s0 * (1.f / (float)En);
    o.y = s1 * (1.f / (float)En);
    o.z = s2 * (1.f / (float)En);
    o.w = s3 * (1.f / (float)En);
    reinterpret_cast<float4*>(g_spatial + b * Nn + g * 4)[0] = o;
}

// --------- kernel 3: batched Gram, split-K=4, 4-warp CTAs, 64x64 warp tiles ---------
// Epilogue: stage fp32 tile in smem, emit bf16 partials; mirror rows coalesced.
__global__ void __launch_bounds__(128, 2) k_gemm(int boff) {
    extern __shared__ __align__(16) char dyn[];
    const uint32_t dynb = s2u(dyn);

    const int ti_tab[10] = {0, 0, 0, 0, 1, 1, 1, 2, 2, 3};
    const int tj_tab[10] = {0, 1, 2, 3, 1, 2, 3, 2, 3, 3};
    const int pair = blockIdx.x >> 2;
    const int ks = blockIdx.x & 3;
    const int ti = ti_tab[pair];
    const int tj = tj_tab[pair];
    const bool diag = (ti == tj);
    const int b = blockIdx.y + boff;
    const int t = threadIdx.x;
    const int wid = t >> 5;
    const int lane = t & 31;
    const int wm = wid >> 1;   // 0..1 : 64-row strip
    const int wn = wid & 1;    // 0..1 : 64-col strip

    const __nv_bfloat16* X = g_xbf + (size_t)b * En * Nn;
    const char* Arows = (const char*)(X + (size_t)ti * 128 * Nn);
    const char* Brows = (const char*)(X + (size_t)tj * 128 * Nn);
    const int cbase = ks * CHUNKS_PER_ITEM;

    const int r0q = t >> 3;   // row base 0..15 (+16*q)
    const int sg = t & 7;     // 16B segment within 128B chunk row

    wmma::fragment<wmma::accumulator, 16, 16, 16, float> acc[4][4];
#pragma unroll
    for (int i = 0; i < 4; i++)
#pragma unroll
        for (int j = 0; j < 4; j++) wmma::fill_fragment(acc[i][j], 0.f);

    // ---- prologue: prefetch chunks 0,1 of this quarter ----
#pragma unroll
    for (int j = 0; j < 2; j++) {
        uint32_t sb = dynb + j * STAGE_BYTES;
#pragma unroll
        for (int q = 0; q < 8; q++) {
            int r = r0q + 16 * q;
            uint32_t off = (uint32_t)(r * (LDT * 2) + sg * 16);
            cp16(sb + off,
                 Arows + (size_t)r * 8192 + (size_t)(cbase + j) * 128 + sg * 16);
            if (!diag)
                cp16(sb + TILE_BYTES + off,
                     Brows + (size_t)r * 8192 + (size_t)(cbase + j) * 128 + sg * 16);
        }
        cp_commit();
    }

    for (int i = 0; i < CHUNKS_PER_ITEM; i++) {
        cp_wait1();
        __syncthreads();

        const int jn = i + 2;
        if (jn < CHUNKS_PER_ITEM) {
            uint32_t sb = dynb + (jn % STAGES) * STAGE_BYTES;
#pragma unroll
            for (int q = 0; q < 8; q++) {
                int r = r0q + 16 * q;
                uint32_t off = (uint32_t)(r * (LDT * 2) + sg * 16);
                cp16(sb + off,
                     Arows + (size_t)r * 8192 + (size_t)(cbase + jn) * 128 + sg * 16);
                if (!diag)
                    cp16(sb + TILE_BYTES + off,
                         Brows + (size_t)r * 8192 + (size_t)(cbase + jn) * 128 + sg * 16);
            }
        }
        cp_commit();

        const int st = i % STAGES;
        const __nv_bfloat16* sA =
            reinterpret_cast<const __nv_bfloat16*>(dyn + st * STAGE_BYTES);
        const __nv_bfloat16* sB = diag ? sA : (sA + 128 * LDT);

        wmma::fragment<wmma::matrix_a, 16, 16, 16, __nv_bfloat16,
                       wmma::row_major> af[2][4];
        wmma::fragment<wmma::matrix_b, 16, 16, 16, __nv_bfloat16,
                       wmma::col_major> bf[2][4];
#pragma unroll
        for (int x = 0; x < 4; x++)
            wmma::load_matrix_sync(af[0][x], &sA[(wm * 64 + x * 16) * LDT], LDT);
#pragma unroll
        for (int y = 0; y < 4; y++)
            wmma::load_matrix_sync(bf[0][y], &sB[(wn * 64 + y * 16) * LDT], LDT);

#pragma unroll
        for (int kk = 0; kk < 4; kk++) {
            const int cur = kk & 1, nxt = cur ^ 1;
            if (kk < 3) {
#pragma unroll
                for (int x = 0; x < 4; x++)
                    wmma::load_matrix_sync(
                        af[nxt][x], &sA[(wm * 64 + x * 16) * LDT + (kk + 1) * 16], LDT);
#pragma unroll
                for (int y = 0; y < 4; y++)
                    wmma::load_matrix_sync(
                        bf[nxt][y], &sB[(wn * 64 + y * 16) * LDT + (kk + 1) * 16], LDT);
            }
#pragma unroll
            for (int x = 0; x < 4; x++)
#pragma unroll
                for (int y = 0; y < 4; y++)
                    wmma::mma_sync(acc[x][y], af[cur][x], bf[cur][y], acc[x][y]);
        }
    }
    cp_wait0();
    __syncthreads();   // all warps done with stage buffers before reuse

    // ---- epilogue: smem-stage fp32 tile, emit bf16 (direct + coalesced mirror) ----
    float* stage = (float*)dyn + wid * (64 * STG_PITCH);
#pragma unroll
    for (int x = 0; x < 4; x++)
#pragma unroll
        for (int y = 0; y < 4; y++)
            wmma::store_matrix_sync(&stage[(x * 16) * STG_PITCH + y * 16],
                                    acc[x][y], STG_PITCH, wmma::mem_row_major);
    __syncwarp();

    __nv_bfloat16* C = g_partb + (size_t)ks * Bn * En * En + (size_t)b * En * En;
    const int rm0 = ti * 128 + wm * 64;
    const int cn0 = tj * 128 + wn * 64;
#pragma unroll 4
    for (int r = 0; r < 64; r++) {
        float2 v = *reinterpret_cast<const float2*>(&stage[r * STG_PITCH + 2 * lane]);
        __nv_bfloat162 h = __floats2bfloat162_rn(v.x, v.y);
        *reinterpret_cast<__nv_bfloat162*>(
            &C[(size_t)(rm0 + r) * En + cn0 + 2 * lane]) = h;
    }
    if (!diag) {
#pragma unroll 4
        for (int c = 0; c < 64; c++) {
            float a0 = stage[(2 * lane) * STG_PITCH + c];
            float a1 = stage[(2 * lane + 1) * STG_PITCH + c];
            __nv_bfloat162 h = __floats2bfloat162_rn(a0, a1);
            *reinterpret_cast<__nv_bfloat162*>(
                &C[(size_t)(cn0 + c) * En + rm0 + 2 * lane]) = h;
        }
    }
}

// ---------------- kernel 4: bilinear resize + per-view min/max ----------------
__global__ void __launch_bounds__(256) k_resize(float* __restrict__ out, int voff) {
    const int v = blockIdx.y + voff;
    const int id = blockIdx.x * 256 + threadIdx.x;
    const int b = id / (IMG * IMG);
    const int rem = id % (IMG * IMG);
    const int y = rem / IMG;
    const int xw = rem - y * IMG;

    const int size = (v == 0) ? 23 : (v == 1) ? 64 : 512;
    const float scale = (float)size / (float)IMG;

    float rr = fmaxf(((float)y + 0.5f) * scale - 0.5f, 0.f);
    int r0 = min((int)floorf(rr), size - 1);
    int r1 = min(r0 + 1, size - 1);
    float wr = rr - (float)r0;
    float cc = fmaxf(((float)xw + 0.5f) * scale - 0.5f, 0.f);
    int c0 = min((int)floorf(cc), size - 1);
    int c1 = min(c0 + 1, size - 1);
    float wc = cc - (float)c0;

    float v00, v01, v10, v11;
    if (v == 0) {
        const float* M = g_mean + b * En;
        int g00 = r0 * 23 + c0, g01 = r0 * 23 + c1, g10 = r1 * 23 + c0, g11 = r1 * 23 + c1;
        v00 = (g00 < En) ? M[g00] : 0.f;
        v01 = (g01 < En) ? M[g01] : 0.f;
        v10 = (g10 < En) ? M[g10] : 0.f;
        v11 = (g11 < En) ? M[g11] : 0.f;
    } else if (v == 1) {
        const float* S = g_spatial + b * Nn;
        v00 = S[r0 * 64 + c0]; v01 = S[r0 * 64 + c1];
        v10 = S[r1 * 64 + c0]; v11 = S[r1 * 64 + c1];
    } else {
        const __nv_bfloat16* P = g_partb + (size_t)b * En * En;
        const size_t SP = (size_t)Bn * En * En;
        const float* M = g_mean + b * En;
        const float* I = g_inv + b * En;
        float m0 = M[r0], m1 = M[r1], i0 = I[r0], i1 = I[r1];
        float mc0 = M[c0], mc1 = M[c1], ic0 = I[c0], ic1 = I[c1];
        size_t o00 = (size_t)r0 * En + c0, o01 = (size_t)r0 * En + c1;
        size_t o10 = (size_t)r1 * En + c0, o11 = (size_t)r1 * En + c1;
        float g00 = __bfloat162float(P[o00]) + __bfloat162float(P[o00 + SP]) +
                    __bfloat162float(P[o00 + 2 * SP]) + __bfloat162float(P[o00 + 3 * SP]);
        float g01 = __bfloat162float(P[o01]) + __bfloat162float(P[o01 + SP]) +
                    __bfloat162float(P[o01 + 2 * SP]) + __bfloat162float(P[o01 + 3 * SP]);
        float g10 = __bfloat162float(P[o10]) + __bfloat162float(P[o10 + SP]) +
                    __bfloat162float(P[o10 + 2 * SP]) + __bfloat162float(P[o10 + 3 * SP]);
        float g11 = __bfloat162float(P[o11]) + __bfloat162float(P[o11 + SP]) +
                    __bfloat162float(P[o11 + 2 * SP]) + __bfloat162float(P[o11 + 3 * SP]);
        v00 = (g00 - (float)Nn * m0 * mc0) * i0 * ic0;
        v01 = (g01 - (float)Nn * m0 * mc1) * i0 * ic1;
        v10 = (g10 - (float)Nn * m1 * mc0) * i1 * ic0;
        v11 = (g11 - (float)Nn * m1 * mc1) * i1 * ic1;
    }
    float top = v00 * (1.f - wc) + v01 * wc;
    float bot = v10 * (1.f - wc) + v11 * wc;
    float val = top * (1.f - wr) + bot * wr;

    out[((size_t)b * 3 + v) * (IMG * IMG) + rem] = val;

    float mn = val, mx = val;
#pragma unroll
    for (int o = 16; o; o >>= 1) {
        mn = fminf(mn, __shfl_down_sync(0xFFFFFFFFu, mn, o));
        mx = fmaxf(mx, __shfl_down_sync(0xFFFFFFFFu, mx, o));
    }
    __shared__ float smn[8], smx[8];
    int w = threadIdx.x >> 5, l = threadIdx.x & 31;
    if (l == 0) { smn[w] = mn; smx[w] = mx; }
    __syncthreads();
    if (threadIdx.x == 0) {
        float bmn = smn[0], bmx = smx[0];
#pragma unroll
        for (int i = 1; i < 8; i++) {
            bmn = fminf(bmn, smn[i]);
            bmx = fmaxf(bmx, smx[i]);
        }
        atomicMin(&g_mm[v * 2], fenc(bmn));
        atomicMax(&g_mm[v * 2 + 1], fenc(bmx));
    }
}

// ------------------------- kernel 5: normalize -------------------------
__global__ void __launch_bounds__(256) k_norm(float* __restrict__ out, int voff) {
    const int v = blockIdx.y + voff;
    const int id = blockIdx.x * 256 + threadIdx.x;
    const int b = id / (IMG * IMG);
    const int rem = id % (IMG * IMG);
    float mn = fdec(g_mm[v * 2]);
    float mx = fdec(g_mm[v * 2 + 1]);
    float span = mx - mn;
    size_t o = ((size_t)b * 3 + v) * (IMG * IMG) + rem;
    float val = out[o];
    out[o] = (span < 1e-8f) ? 0.f : (val - mn) / (span + 1e-8f);
}

// ----------------------------- launch (exact R10 schedule) -----------------------------
extern "C" void kernel_launch(void* const* d_in, const int* in_sizes, int n_in,
                              void* d_out, int out_size) {
    const float* x = (const float*)d_in[0];
    float* out = (float*)d_out;

    static int configured = 0;
    static cudaStream_t s1;
    static cudaEvent_t eA, eB, eS1;
    if (!configured) {
        cudaFuncSetAttribute(k_gemm, cudaFuncAttributeMaxDynamicSharedMemorySize,
                             GEMM_SMEM);
        cudaStreamCreateWithFlags(&s1, cudaStreamNonBlocking);
        cudaEventCreateWithFlags(&eA, cudaEventDisableTiming);
        cudaEventCreateWithFlags(&eB, cudaEventDisableTiming);
        cudaEventCreateWithFlags(&eS1, cudaEventDisableTiming);
        configured = 1;
    }

    const int pix_blocks = (Bn * IMG * IMG) / 256;  // 6272

    // --- main stream: init + rowstats for batches [0, BSPLIT_A) ---
    k_init<<<1, 32>>>();
    k_rowstats<<<BSPLIT_A * En, 256>>>(x, 0);
    cudaEventRecord(eA, 0);

    // --- side stream: remaining rowstats, colmean, light views ---
    cudaStreamWaitEvent(s1, eA, 0);
    k_rowstats<<<BSPLIT_B * En, 256, 0, s1>>>(x, BSPLIT_A * En);
    cudaEventRecord(eB, s1);
    k_colmean<<<128, 256, 0, s1>>>();
    k_resize<<<dim3(pix_blocks, 2), 256, 0, s1>>>(out, 0);  // views 0,1
    k_norm<<<dim3(pix_blocks, 2), 256, 0, s1>>>(out, 0);
    cudaEventRecord(eS1, s1);

    // --- main stream: GEMM A (2 waves), GEMM B (3 waves), correlation view ---
    k_gemm<<<dim3(10 * KSPLIT, BSPLIT_A), 128, GEMM_SMEM>>>(0);
    cudaStreamWaitEvent(0, eB, 0);
    k_gemm<<<dim3(10 * KSPLIT, BSPLIT_B), 128, GEMM_SMEM>>>(BSPLIT_A);
    k_resize<<<dim3(pix_blocks, 1), 256>>>(out, 2);          // view 2
    k_norm<<<dim3(pix_blocks, 1), 256>>>(out, 2);

    cudaStreamWaitEvent(0, eS1, 0);
}

// round 15
// speedup vs baseline: 1.0632x; 1.0632x over previous
#include <cuda_runtime.h>
#include <cuda_bf16.h>
#include <mma.h>
#include <cstdint>

using namespace nvcuda;

#define Bn 32
#define En 512
#define Nn 4096
#define IMG 224

#define KC 64                    // K elements per chunk
#define KSPLIT 4
#define CHUNKS_PER_ITEM 16       // 64 chunks / 4 splits
#define STAGES 3
#define LDT 72                   // padded smem leading dim (elements)
#define TILE_BYTES (128 * LDT * 2)          // 18432 per operand tile
#define STAGE_BYTES (2 * TILE_BYTES)        // 36864 (A + B)
#define GEMM_SMEM (STAGES * STAGE_BYTES)    // 110592

#define BSPLIT_A 14              // 560 CTAs = 2 waves at 296 slots (R10-proven)
#define BSPLIT_B (Bn - BSPLIT_A) // 720 CTAs = 3 waves

// ----------------------------- device scratch -----------------------------
__device__ __nv_bfloat16 g_xbf[(size_t)Bn * En * Nn];       // 134 MB bf16 copy
__device__ float g_mean[Bn * En];                            // row means
__device__ float g_inv[Bn * En];                             // 1/(||x-mean||+1e-8)
__device__ float g_spatial[Bn * Nn];                         // column means
__device__ float g_part[(size_t)KSPLIT * Bn * En * En];      // 134 MB Gram partials
__device__ unsigned g_mm[6];                                 // encoded min/max per view

// ----------------------------- helpers -----------------------------
__device__ __forceinline__ unsigned fenc(float f) {
    unsigned u = __float_as_uint(f);
    return (u & 0x80000000u) ? ~u : (u | 0x80000000u);
}
__device__ __forceinline__ float fdec(unsigned e) {
    return (e & 0x80000000u) ? __uint_as_float(e ^ 0x80000000u)
                             : __uint_as_float(~e);
}
__device__ __forceinline__ uint32_t s2u(const void* p) {
    uint32_t a;
    asm("{ .reg .u64 t; cvta.to.shared.u64 t, %1; cvt.u32.u64 %0, t; }"
        : "=r"(a) : "l"(p));
    return a;
}
__device__ __forceinline__ void cp16(uint32_t dst, const void* src) {
    asm volatile("cp.async.cg.shared.global [%0], [%1], 16;" :: "r"(dst), "l"(src));
}
__device__ __forceinline__ void cp_commit() {
    asm volatile("cp.async.commit_group;" ::: "memory");
}
__device__ __forceinline__ void cp_wait1() {
    asm volatile("cp.async.wait_group 1;" ::: "memory");
}
__device__ __forceinline__ void cp_wait0() {
    asm volatile("cp.async.wait_group 0;" ::: "memory");
}

// ------------------- kernel 1: row stats + bf16 convert (row ranges) -------------------
// Block 0 of the roff==0 launch also initializes the min/max slots (saves k_init).
// All 16 float4 loads are issued before any conversion math (MLP 16/thread).
__global__ void __launch_bounds__(256) k_rowstats(const float* __restrict__ x, int roff) {
    if (roff == 0 && blockIdx.x == 0 && threadIdx.x < 6)
        g_mm[threadIdx.x] = (threadIdx.x & 1) ? 0u : 0xFFFFFFFFu;

    const int row = blockIdx.x + roff;
    const float4* src = reinterpret_cast<const float4*>(x) + (size_t)row * (Nn / 4);
    uint2* dst = reinterpret_cast<uint2*>(g_xbf) + (size_t)row * (Nn / 4);

    float4 v[4];
#pragma unroll
    for (int k = 0; k < 4; k++) v[k] = src[threadIdx.x + k * 256];

    float s = 0.f, ss = 0.f;
#pragma unroll
    for (int k = 0; k < 4; k++) {
        s += v[k].x + v[k].y + v[k].z + v[k].w;
        ss += v[k].x * v[k].x + v[k].y * v[k].y + v[k].z * v[k].z + v[k].w * v[k].w;
        unsigned ax = (unsigned)__bfloat16_as_ushort(__float2bfloat16_rn(v[k].x));
        unsigned ay = (unsigned)__bfloat16_as_ushort(__float2bfloat16_rn(v[k].y));
        unsigned az = (unsigned)__bfloat16_as_ushort(__float2bfloat16_rn(v[k].z));
        unsigned aw = (unsigned)__bfloat16_as_ushort(__float2bfloat16_rn(v[k].w));
        uint2 o;
        o.x = ax | (ay << 16);
        o.y = az | (aw << 16);
        dst[threadIdx.x + k * 256] = o;
    }
#pragma unroll
    for (int o = 16; o; o >>= 1) {
        s += __shfl_down_sync(0xFFFFFFFFu, s, o);
        ss += __shfl_down_sync(0xFFFFFFFFu, ss, o);
    }
    __shared__ float sh[16];
    int w = threadIdx.x >> 5, l = threadIdx.x & 31;
    if (l == 0) { sh[w] = s; sh[w + 8] = ss; }
    __syncthreads();
    if (threadIdx.x == 0) {
        float S = 0.f, SS = 0.f;
#pragma unroll
        for (int i = 0; i < 8; i++) { S += sh[i]; SS += sh[i + 8]; }
        float m = S * (1.f / (float)Nn);
        g_mean[row] = m;
        float var = SS - S * m;
        float r = sqrtf(fmaxf(var, 0.f));
        g_inv[row] = 1.f / (r + 1e-8f);
    }
}

// ------------------ kernel 2: column means (from bf16 copy) ------------------
__global__ void __launch_bounds__(256) k_colmean() {
    int T = blockIdx.x * 256 + threadIdx.x;   // 0..65535
    int b = T >> 11;                           // batch
    int g = T & 2047;                          // 2-column group
    const unsigned* p = reinterpret_cast<const unsigned*>(g_xbf + (size_t)b * En * Nn) + g;
    float s0 = 0.f, s1 = 0.f;
#pragma unroll 8
    for (int e = 0; e < En; e++) {
        unsigned v = p[(size_t)e * (Nn / 2)];
        s0 += __uint_as_float(v << 16);
        s1 += __uint_as_float(v & 0xFFFF0000u);
    }
    float2 o;
    o.x = s0 * (1.f / (float)En);
    o.y = s1 * (1.f / (float)En);
    reinterpret_cast<float2*>(g_spatial + b * Nn + g * 2)[0] = o;
}

// --------- kernel 3: batched Gram, split-K=4, 4-warp CTAs, 64x64 warp tiles ---------
// Mirror stores (hidden under compute / L2 write-merged). R10-proven.
__global__ void __launch_bounds__(128, 2) k_gemm(int boff) {
    extern __shared__ __align__(16) char dyn[];
    const uint32_t dynb = s2u(dyn);

    const int ti_tab[10] = {0, 0, 0, 0, 1, 1, 1, 2, 2, 3};
    const int tj_tab[10] = {0, 1, 2, 3, 1, 2, 3, 2, 3, 3};
    const int pair = blockIdx.x >> 2;
    const int ks = blockIdx.x & 3;
    const int ti = ti_tab[pair];
    const int tj = tj_tab[pair];
    const bool diag = (ti == tj);
    const int b = blockIdx.y + boff;
    const int t = threadIdx.x;
    const int wid = t >> 5;
    const int wm = wid >> 1;   // 0..1 : 64-row strip
    const int wn = wid & 1;    // 0..1 : 64-col strip

    const __nv_bfloat16* X = g_xbf + (size_t)b * En * Nn;
    const char* Arows = (const char*)(X + (size_t)ti * 128 * Nn);
    const char* Brows = (const char*)(X + (size_t)tj * 128 * Nn);
    const int cbase = ks * CHUNKS_PER_ITEM;

    const int r0q = t >> 3;   // row base 0..15 (+16*q)
    const int sg = t & 7;     // 16B segment within 128B chunk row

    wmma::fragment<wmma::accumulator, 16, 16, 16, float> acc[4][4];
#pragma unroll
    for (int i = 0; i < 4; i++)
#pragma unroll
        for (int j = 0; j < 4; j++) wmma::fill_fragment(acc[i][j], 0.f);

    // ---- prologue: prefetch chunks 0,1 of this quarter ----
#pragma unroll
    for (int j = 0; j < 2; j++) {
        uint32_t sb = dynb + j * STAGE_BYTES;
#pragma unroll
        for (int q = 0; q < 8; q++) {
            int r = r0q + 16 * q;
            uint32_t off = (uint32_t)(r * (LDT * 2) + sg * 16);
            cp16(sb + off,
                 Arows + (size_t)r * 8192 + (size_t)(cbase + j) * 128 + sg * 16);
            if (!diag)
                cp16(sb + TILE_BYTES + off,
                     Brows + (size_t)r * 8192 + (size_t)(cbase + j) * 128 + sg * 16);
        }
        cp_commit();
    }

    for (int i = 0; i < CHUNKS_PER_ITEM; i++) {
        cp_wait1();
        __syncthreads();

        const int jn = i + 2;
        if (jn < CHUNKS_PER_ITEM) {
            uint32_t sb = dynb + (jn % STAGES) * STAGE_BYTES;
#pragma unroll
            for (int q = 0; q < 8; q++) {
                int r = r0q + 16 * q;
                uint32_t off = (uint32_t)(r * (LDT * 2) + sg * 16);
                cp16(sb + off,
                     Arows + (size_t)r * 8192 + (size_t)(cbase + jn) * 128 + sg * 16);
                if (!diag)
                    cp16(sb + TILE_BYTES + off,
                         Brows + (size_t)r * 8192 + (size_t)(cbase + jn) * 128 + sg * 16);
            }
        }
        cp_commit();

        const int st = i % STAGES;
        const __nv_bfloat16* sA =
            reinterpret_cast<const __nv_bfloat16*>(dyn + st * STAGE_BYTES);
        const __nv_bfloat16* sB = diag ? sA : (sA + 128 * LDT);

        wmma::fragment<wmma::matrix_a, 16, 16, 16, __nv_bfloat16,
                       wmma::row_major> af[2][4];
        wmma::fragment<wmma::matrix_b, 16, 16, 16, __nv_bfloat16,
                       wmma::col_major> bf[2][4];
#pragma unroll
        for (int x = 0; x < 4; x++)
            wmma::load_matrix_sync(af[0][x], &sA[(wm * 64 + x * 16) * LDT], LDT);
#pragma unroll
        for (int y = 0; y < 4; y++)
            wmma::load_matrix_sync(bf[0][y], &sB[(wn * 64 + y * 16) * LDT], LDT);

#pragma unroll
        for (int kk = 0; kk < 4; kk++) {
            const int cur = kk & 1, nxt = cur ^ 1;
            if (kk < 3) {
#pragma unroll
                for (int x = 0; x < 4; x++)
                    wmma::load_matrix_sync(
                        af[nxt][x], &sA[(wm * 64 + x * 16) * LDT + (kk + 1) * 16], LDT);
#pragma unroll
                for (int y = 0; y < 4; y++)
                    wmma::load_matrix_sync(
                        bf[nxt][y], &sB[(wn * 64 + y * 16) * LDT + (kk + 1) * 16], LDT);
            }
#pragma unroll
            for (int x = 0; x < 4; x++)
#pragma unroll
                for (int y = 0; y < 4; y++)
                    wmma::mma_sync(acc[x][y], af[cur][x], bf[cur][y], acc[x][y]);
        }
    }
    cp_wait0();

    // ---- epilogue: direct + mirrored stores into this split's partial ----
    float* C = g_part + (size_t)ks * Bn * En * En + (size_t)b * En * En;
#pragma unroll
    for (int x = 0; x < 4; x++) {
#pragma unroll
        for (int y = 0; y < 4; y++) {
            int rm = ti * 128 + wm * 64 + x * 16;
            int cn = tj * 128 + wn * 64 + y * 16;
            wmma::store_matrix_sync(&C[(size_t)rm * En + cn], acc[x][y], En,
                                    wmma::mem_row_major);
            if (!diag)
                wmma::store_matrix_sync(&C[(size_t)cn * En + rm], acc[x][y], En,
                                        wmma::mem_col_major);
        }
    }
}

// ---------------- kernel 4: bilinear resize + per-view min/max ----------------
__global__ void __launch_bounds__(256) k_resize(float* __restrict__ out, int voff) {
    const int v = blockIdx.y + voff;
    const int id = blockIdx.x * 256 + threadIdx.x;
    const int b = id / (IMG * IMG);
    const int rem = id % (IMG * IMG);
    const int y = rem / IMG;
    const int xw = rem - y * IMG;

    const int size = (v == 0) ? 23 : (v == 1) ? 64 : 512;
    const float scale = (float)size / (float)IMG;

    float rr = fmaxf(((float)y + 0.5f) * scale - 0.5f, 0.f);
    int r0 = min((int)floorf(rr), size - 1);
    int r1 = min(r0 + 1, size - 1);
    float wr = rr - (float)r0;
    float cc = fmaxf(((float)xw + 0.5f) * scale - 0.5f, 0.f);
    int c0 = min((int)floorf(cc), size - 1);
    int c1 = min(c0 + 1, size - 1);
    float wc = cc - (float)c0;

    float v00, v01, v10, v11;
    if (v == 0) {
        const float* M = g_mean + b * En;
        int g00 = r0 * 23 + c0, g01 = r0 * 23 + c1, g10 = r1 * 23 + c0, g11 = r1 * 23 + c1;
        v00 = (g00 < En) ? M[g00] : 0.f;
        v01 = (g01 < En) ? M[g01] : 0.f;
        v10 = (g10 < En) ? M[g10] : 0.f;
        v11 = (g11 < En) ? M[g11] : 0.f;
    } else if (v == 1) {
        const float* S = g_spatial + b * Nn;
        v00 = S[r0 * 64 + c0]; v01 = S[r0 * 64 + c1];
        v10 = S[r1 * 64 + c0]; v11 = S[r1 * 64 + c1];
    } else {
        const float* P = g_part + (size_t)b * En * En;
        const size_t SP = (size_t)Bn * En * En;
        const float* M = g_mean + b * En;
        const float* I = g_inv + b * En;
        float m0 = M[r0], m1 = M[r1], i0 = I[r0], i1 = I[r1];
        float mc0 = M[c0], mc1 = M[c1], ic0 = I[c0], ic1 = I[c1];
        size_t o00 = (size_t)r0 * En + c0, o01 = (size_t)r0 * En + c1;
        size_t o10 = (size_t)r1 * En + c0, o11 = (size_t)r1 * En + c1;
        float g00 = P[o00] + P[o00 + SP] + P[o00 + 2 * SP] + P[o00 + 3 * SP];
        float g01 = P[o01] + P[o01 + SP] + P[o01 + 2 * SP] + P[o01 + 3 * SP];
        float g10 = P[o10] + P[o10 + SP] + P[o10 + 2 * SP] + P[o10 + 3 * SP];
        float g11 = P[o11] + P[o11 + SP] + P[o11 + 2 * SP] + P[o11 + 3 * SP];
        v00 = (g00 - (float)Nn * m0 * mc0) * i0 * ic0;
        v01 = (g01 - (float)Nn * m0 * mc1) * i0 * ic1;
        v10 = (g10 - (float)Nn * m1 * mc0) * i1 * ic0;
        v11 = (g11 - (float)Nn * m1 * mc1) * i1 * ic1;
    }
    float top = v00 * (1.f - wc) + v01 * wc;
    float bot = v10 * (1.f - wc) + v11 * wc;
    float val = top * (1.f - wr) + bot * wr;

    out[((size_t)b * 3 + v) * (IMG * IMG) + rem] = val;

    float mn = val, mx = val;
#pragma unroll
    for (int o = 16; o; o >>= 1) {
        mn = fminf(mn, __shfl_down_sync(0xFFFFFFFFu, mn, o));
        mx = fmaxf(mx, __shfl_down_sync(0xFFFFFFFFu, mx, o));
    }
    __shared__ float smn[8], smx[8];
    int w = threadIdx.x >> 5, l = threadIdx.x & 31;
    if (l == 0) { smn[w] = mn; smx[w] = mx; }
    __syncthreads();
    if (threadIdx.x == 0) {
        float bmn = smn[0], bmx = smx[0];
#pragma unroll
        for (int i = 1; i < 8; i++) {
            bmn = fminf(bmn, smn[i]);
            bmx = fmaxf(bmx, smx[i]);
        }
        atomicMin(&g_mm[v * 2], fenc(bmn));
        atomicMax(&g_mm[v * 2 + 1], fenc(bmx));
    }
}

// ------------------------- kernel 5: normalize -------------------------
__global__ void __launch_bounds__(256) k_norm(float* __restrict__ out, int voff) {
    const int v = blockIdx.y + voff;
    const int id = blockIdx.x * 256 + threadIdx.x;
    const int b = id / (IMG * IMG);
    const int rem = id % (IMG * IMG);
    float mn = fdec(g_mm[v * 2]);
    float mx = fdec(g_mm[v * 2 + 1]);
    float span = mx - mn;
    size_t o = ((size_t)b * 3 + v) * (IMG * IMG) + rem;
    float val = out[o];
    out[o] = (span < 1e-8f) ? 0.f : (val - mn) / (span + 1e-8f);
}

// ----------------------------- launch (R10 schedule, k_init folded) -----------------------------
extern "C" void kernel_launch(void* const* d_in, const int* in_sizes, int n_in,
                              void* d_out, int out_size) {
    const float* x = (const float*)d_in[0];
    float* out = (float*)d_out;

    static int configured = 0;
    static cudaStream_t s1;
    static cudaEvent_t eA, eB, eS1;
    if (!configured) {
        cudaFuncSetAttribute(k_gemm, cudaFuncAttributeMaxDynamicSharedMemorySize,
                             GEMM_SMEM);
        cudaStreamCreateWithFlags(&s1, cudaStreamNonBlocking);
        cudaEventCreateWithFlags(&eA, cudaEventDisableTiming);
        cudaEventCreateWithFlags(&eB, cudaEventDisableTiming);
        cudaEventCreateWithFlags(&eS1, cudaEventDisableTiming);
        configured = 1;
    }

    const int pix_blocks = (Bn * IMG * IMG) / 256;  // 6272

    // --- main stream: rowstats for batches [0, BSPLIT_A) (block 0 inits g_mm) ---
    k_rowstats<<<BSPLIT_A * En, 256>>>(x, 0);
    cudaEventRecord(eA, 0);

    // --- side stream: remaining rowstats, colmean, light views ---
    cudaStreamWaitEvent(s1, eA, 0);
    k_rowstats<<<BSPLIT_B * En, 256, 0, s1>>>(x, BSPLIT_A * En);
    cudaEventRecord(eB, s1);
    k_colmean<<<256, 256, 0, s1>>>();
    k_resize<<<dim3(pix_blocks, 2), 256, 0, s1>>>(out, 0);  // views 0,1
    k_norm<<<dim3(pix_blocks, 2), 256, 0, s1>>>(out, 0);
    cudaEventRecord(eS1, s1);

    // --- main stream: GEMM A (2 waves), GEMM B (3 waves), correlation view ---
    k_gemm<<<dim3(10 * KSPLIT, BSPLIT_A), 128, GEMM_SMEM>>>(0);
    cudaStreamWaitEvent(0, eB, 0);
    k_gemm<<<dim3(10 * KSPLIT, BSPLIT_B), 128, GEMM_SMEM>>>(BSPLIT_A);
    k_resize<<<dim3(pix_blocks, 1), 256>>>(out, 2);          // view 2
    k_norm<<<dim3(pix_blocks, 1), 256>>>(out, 2);

    cudaStreamWaitEvent(0, eS1, 0);
}